// round 17
// baseline (speedup 1.0000x reference)
#include <cuda_runtime.h>
#include <cuda_bf16.h>
#include <math.h>
#include <stdint.h>

#define B_ 4
#define S_ 2048
#define D_ 256
#define H_ 4
#define HD_ 64
#define NROWS (B_ * S_)

// ---------------- cp.async helpers ---------------------------------------
#define CP16(dst_u32, src_ptr) \
    asm volatile("cp.async.cg.shared.global [%0], [%1], 16;" :: "r"(dst_u32), "l"(src_ptr) : "memory")
#define CPCOMMIT() asm volatile("cp.async.commit_group;" ::: "memory")
#define CPWAIT0()  asm volatile("cp.async.wait_group 0;" ::: "memory")

// ---------------- bf16 mma helpers ---------------------------------------
__device__ __forceinline__ uint32_t pkbf(float lo, float hi) {
    __nv_bfloat162 h = __floats2bfloat162_rn(lo, hi);
    return *reinterpret_cast<uint32_t*>(&h);
}
__device__ __forceinline__ void mma_bf16(float* d, const uint32_t* a, uint32_t b0, uint32_t b1) {
    asm volatile(
        "mma.sync.aligned.m16n8k16.row.col.f32.bf16.bf16.f32 "
        "{%0,%1,%2,%3}, {%4,%5,%6,%7}, {%8,%9}, {%0,%1,%2,%3};"
        : "+f"(d[0]), "+f"(d[1]), "+f"(d[2]), "+f"(d[3])
        : "r"(a[0]), "r"(a[1]), "r"(a[2]), "r"(a[3]), "r"(b0), "r"(b1));
}

// ---------------- scratch (no allocation allowed) ----------------
__device__ __align__(16) float g_x1[NROWS * D_];
__device__ __align__(16) __nv_bfloat16 g_hhi[NROWS * D_];
__device__ __align__(16) __nv_bfloat16 g_hlo[NROWS * D_];
__device__ __align__(16) float g_q [NROWS * D_];
__device__ __align__(16) float g_k [NROWS * D_];
__device__ __align__(16) __nv_bfloat16 g_vt[NROWS * D_];  // [bh][d][s]
__device__ __align__(16) float g_o [NROWS * D_];
__device__ __align__(16) float g_sin[S_ * 32];
__device__ __align__(16) float g_cos[S_ * 32];
__device__ __align__(16) __nv_bfloat16 g_wthi[5 * 65536]; // W^T hi: [wid][n][k]
__device__ __align__(16) __nv_bfloat16 g_wtlo[5 * 65536]; // W^T lo
__device__ int g_idx[B_ * S_];
__device__ int g_cnt[B_];

// ---------------- RoPE tables --------------------------------------------
__global__ void k_rope_tab() {
    int idx = blockIdx.x * blockDim.x + threadIdx.x;
    if (idx >= S_ * 32) return;
    int s = idx >> 5, j = idx & 31;
    float ivf = (float)exp(-(double)(2 * j) / 64.0 * 9.210340371976184);
    float ang = (float)s * ivf;
    double ad = (double)ang;
    g_sin[idx] = (float)sin(ad);
    g_cos[idx] = (float)cos(ad);
}

// ---------------- split weights into transposed bf16 hi/lo ---------------
__global__ void k_wsplit(const float* __restrict__ w0, const float* __restrict__ w1,
                         const float* __restrict__ w2, const float* __restrict__ w3,
                         const float* __restrict__ w4) {
    const float* srcs[5] = {w0, w1, w2, w3, w4};
    const int wid = blockIdx.y, k = blockIdx.x, n = threadIdx.x;
    float v = srcs[wid][k * 256 + n];
    __nv_bfloat16 h = __float2bfloat16_rn(v);
    int o = wid * 65536 + n * 256 + k;
    g_wthi[o] = h;
    g_wtlo[o] = __float2bfloat16_rn(v - __bfloat162float(h));
}

// ---------------- compact unmasked query indices per batch ---------------
__global__ void k_prep(const int* __restrict__ mask) {
    __shared__ int cnt;
    const int b = blockIdx.x;
    if (threadIdx.x == 0) cnt = 0;
    __syncthreads();
    for (int s = threadIdx.x; s < S_; s += blockDim.x) {
        if (mask[b*S_ + s]) {
            int p = atomicAdd(&cnt, 1);
            g_idx[b*S_ + p] = s;
        }
    }
    __syncthreads();
    if (threadIdx.x == 0) g_cnt[b] = cnt;
}

// ---------------- masked rows get mean(V) over all keys ------------------
__global__ __launch_bounds__(256) void k_fillmean(const int* __restrict__ mask) {
    const int hh = blockIdx.x, b = blockIdx.y;
    const int bh = b*H_ + hh;
    __shared__ float red[4][64];
    __shared__ float mv[64];
    const int d = threadIdx.x >> 2, c = threadIdx.x & 3;
    float s = 0.f;
    const __nv_bfloat16* src = &g_vt[((size_t)bh*HD_ + d)*S_ + c*512];
    for (int t = 0; t < 512; t += 8) {
        uint4 u = *(const uint4*)&src[t];
        const __nv_bfloat162* p2 = (const __nv_bfloat162*)&u;
        #pragma unroll
        for (int j = 0; j < 4; j++)
            s += __bfloat162float(p2[j].x) + __bfloat162float(p2[j].y);
    }
    red[c][d] = s;
    __syncthreads();
    if (c == 0) mv[d] = (red[0][d] + red[1][d] + red[2][d] + red[3][d]) * (1.f/2048.f);
    __syncthreads();
    const int d2 = threadIdx.x & 63, c2 = threadIdx.x >> 6;
    const size_t bhoff = (size_t)bh * S_ * HD_;
    const float m = mv[d2];
    for (int s0 = c2; s0 < S_; s0 += 4) {
        if (!mask[b*S_ + s0]) g_o[bhoff + (size_t)s0*HD_ + d2] = m;
    }
}

// ====== pipelined mma.sync hi/lo GEMM: 64 rows x 256 cols per CTA ========
// smem: A hi/lo 4 chunk-blocks [64][72] each (73728 B) |
//       W hi/lo double-buffered chunks [2][256][72] each (147456 B)
#define MG2_SMEM_BYTES 221184

#define MG2_PROLOG                                                           \
    extern __shared__ char smc[];                                            \
    __nv_bfloat16* AhiP = (__nv_bfloat16*)(smc);                             \
    __nv_bfloat16* AloP = (__nv_bfloat16*)(smc + 36864);                     \
    __nv_bfloat16* WhsP = (__nv_bfloat16*)(smc + 73728);                     \
    __nv_bfloat16* WlsP = (__nv_bfloat16*)(smc + 147456);                    \
    const int tid = threadIdx.x;                                             \
    const int w = tid >> 5, lane = tid & 31;                                 \
    const int grp = lane >> 2, qd = lane & 3;                                \
    const int m0 = (w & 3) * 16, nb = (w >> 2) * 128;                        \
    const int row0 = blockIdx.x * 64;                                        \
    float acc[16][4];                                                        \
    _Pragma("unroll")                                                        \
    for (int j = 0; j < 16; j++) { acc[j][0]=acc[j][1]=acc[j][2]=acc[j][3]=0.f; }

#define MG2_STAGE_W(wbuf, WthP, WtlP, kc) {                                  \
    const __nv_bfloat16* sh = (WthP) + tid*256 + (kc);                       \
    const __nv_bfloat16* sl = (WtlP) + tid*256 + (kc);                       \
    uint32_t dh = (uint32_t)__cvta_generic_to_shared(WhsP + (wbuf)*18432 + tid*72); \
    uint32_t dl = (uint32_t)__cvta_generic_to_shared(WlsP + (wbuf)*18432 + tid*72); \
    _Pragma("unroll")                                                        \
    for (int t = 0; t < 8; t++) { CP16(dh + t*16, sh + t*8); CP16(dl + t*16, sl + t*8); } }

#define MG2_COMPUTE(chblk, wbuf) {                                           \
    uint32_t ah[4][4], al[4][4];                                             \
    const __nv_bfloat16* Ah = AhiP + (chblk)*4608;                           \
    const __nv_bfloat16* Al = AloP + (chblk)*4608;                           \
    _Pragma("unroll")                                                        \
    for (int kt = 0; kt < 4; kt++) {                                         \
        int ko = kt*16 + qd*2;                                               \
        ah[kt][0] = *(const uint32_t*)&Ah[(m0+grp  )*72 + ko];               \
        ah[kt][1] = *(const uint32_t*)&Ah[(m0+grp+8)*72 + ko];               \
        ah[kt][2] = *(const uint32_t*)&Ah[(m0+grp  )*72 + ko+8];             \
        ah[kt][3] = *(const uint32_t*)&Ah[(m0+grp+8)*72 + ko+8];             \
        al[kt][0] = *(const uint32_t*)&Al[(m0+grp  )*72 + ko];               \
        al[kt][1] = *(const uint32_t*)&Al[(m0+grp+8)*72 + ko];               \
        al[kt][2] = *(const uint32_t*)&Al[(m0+grp  )*72 + ko+8];             \
        al[kt][3] = *(const uint32_t*)&Al[(m0+grp+8)*72 + ko+8];             \
    }                                                                        \
    const __nv_bfloat16* WhB = WhsP + (wbuf)*18432;                          \
    const __nv_bfloat16* WlB = WlsP + (wbuf)*18432;                          \
    _Pragma("unroll")                                                        \
    for (int j = 0; j < 16; j++) {                                           \
        const __nv_bfloat16* wh = &WhB[(nb + j*8 + grp)*72];                 \
        const __nv_bfloat16* wl = &WlB[(nb + j*8 + grp)*72];                 \
        _Pragma("unroll")                                                    \
        for (int kt = 0; kt < 4; kt++) {                                     \
            uint32_t bh0 = *(const uint32_t*)&wh[kt*16+qd*2];                \
            uint32_t bh1 = *(const uint32_t*)&wh[kt*16+qd*2+8];              \
            uint32_t bl0 = *(const uint32_t*)&wl[kt*16+qd*2];                \
            uint32_t bl1 = *(const uint32_t*)&wl[kt*16+qd*2+8];              \
            mma_bf16(acc[j], ah[kt], bh0, bh1);                              \
            mma_bf16(acc[j], ah[kt], bl0, bl1);                              \
            mma_bf16(acc[j], al[kt], bh0, bh1);                              \
        }                                                                    \
    } }

// stage ALL of A from an fp32 source (direct convert; arow/kg in scope)
#define MG2_STAGE_A_F32(AEXPR) {                                             \
    const int arow = tid & 63, akq = tid >> 6;                               \
    __nv_bfloat16* Ahb = AhiP + akq*4608 + arow*72;                          \
    __nv_bfloat16* Alb = AloP + akq*4608 + arow*72;                          \
    _Pragma("unroll")                                                        \
    for (int t = 0; t < 16; t++) {                                           \
        const int kk = t*4;                                                  \
        const int kg = akq*64 + kk;                                          \
        float4 a = (AEXPR);                                                  \
        uint32_t h0 = pkbf(a.x, a.y), h1 = pkbf(a.z, a.w);                   \
        __nv_bfloat162 hb0 = *(__nv_bfloat162*)&h0;                          \
        __nv_bfloat162 hb1 = *(__nv_bfloat162*)&h1;                          \
        uint32_t l0 = pkbf(a.x - __bfloat162float(hb0.x), a.y - __bfloat162float(hb0.y)); \
        uint32_t l1 = pkbf(a.z - __bfloat162float(hb1.x), a.w - __bfloat162float(hb1.y)); \
        *(uint2*)&Ahb[kk] = make_uint2(h0, h1);                              \
        *(uint2*)&Alb[kk] = make_uint2(l0, l1);                              \
    } }

// ---------------- K1: x1 = x@w_in + b_in ; h = LN(x1)*g1 + be1 -----------
__global__ __launch_bounds__(256) void k_in_ln(
    const float* __restrict__ X,
    const float* __restrict__ bias, const float* __restrict__ g,
    const float* __restrict__ be)
{
    MG2_PROLOG
    MG2_STAGE_A_F32(*(const float4*)&X[(size_t)(row0 + arow)*256 + kg])
    MG2_STAGE_W(0, g_wthi, g_wtlo, 0)
    CPCOMMIT();
    for (int c = 0; c < 4; c++) {
        CPWAIT0();
        __syncthreads();
        if (c < 3) { MG2_STAGE_W((c+1)&1, g_wthi, g_wtlo, (c+1)*64) CPCOMMIT(); }
        MG2_COMPUTE(c, c&1)
    }
    __syncthreads();

    float s1a=0,s2a=0,s1b=0,s2b=0;
    #pragma unroll
    for (int j = 0; j < 16; j++) {
        int col = nb + j*8 + qd*2;
        float2 bb = *(const float2*)&bias[col];
        acc[j][0]+=bb.x; acc[j][1]+=bb.y; acc[j][2]+=bb.x; acc[j][3]+=bb.y;
        s1a += acc[j][0]+acc[j][1]; s2a += acc[j][0]*acc[j][0]+acc[j][1]*acc[j][1];
        s1b += acc[j][2]+acc[j][3]; s2b += acc[j][2]*acc[j][2]+acc[j][3]*acc[j][3];
    }
    #pragma unroll
    for (int o = 1; o < 4; o <<= 1) {
        s1a += __shfl_xor_sync(~0u,s1a,o); s2a += __shfl_xor_sync(~0u,s2a,o);
        s1b += __shfl_xor_sync(~0u,s1b,o); s2b += __shfl_xor_sync(~0u,s2b,o);
    }
    float2* psum = (float2*)smc;
    if (qd == 0) {
        psum[(m0+grp)*2 + (w>>2)]   = make_float2(s1a, s2a);
        psum[(m0+grp+8)*2 + (w>>2)] = make_float2(s1b, s2b);
    }
    __syncthreads();
    float2 pa0 = psum[(m0+grp)*2],   pa1 = psum[(m0+grp)*2+1];
    float2 pb0 = psum[(m0+grp+8)*2], pb1 = psum[(m0+grp+8)*2+1];
    float mean_a = (pa0.x+pa1.x)*(1.f/256.f);
    float ra = rsqrtf((pa0.y+pa1.y)*(1.f/256.f) - mean_a*mean_a + 1e-5f);
    float mean_b = (pb0.x+pb1.x)*(1.f/256.f);
    float rb = rsqrtf((pb0.y+pb1.y)*(1.f/256.f) - mean_b*mean_b + 1e-5f);
    const size_t r1 = (size_t)row0 + m0 + grp, r2 = r1 + 8;
    #pragma unroll
    for (int j = 0; j < 16; j++) {
        int col = nb + j*8 + qd*2;
        *(float2*)&g_x1[r1*256+col] = make_float2(acc[j][0], acc[j][1]);
        *(float2*)&g_x1[r2*256+col] = make_float2(acc[j][2], acc[j][3]);
        float2 gg = *(const float2*)&g[col], ee = *(const float2*)&be[col];
        float h0 = (acc[j][0]-mean_a)*ra*gg.x + ee.x;
        float h1 = (acc[j][1]-mean_a)*ra*gg.y + ee.y;
        float h2 = (acc[j][2]-mean_b)*rb*gg.x + ee.x;
        float h3 = (acc[j][3]-mean_b)*rb*gg.y + ee.y;
        uint32_t w0 = pkbf(h0,h1); __nv_bfloat162 wb0 = *(__nv_bfloat162*)&w0;
        uint32_t w1 = pkbf(h2,h3); __nv_bfloat162 wb1 = *(__nv_bfloat162*)&w1;
        *(uint32_t*)&g_hhi[r1*256+col] = w0;
        *(uint32_t*)&g_hlo[r1*256+col] = pkbf(h0-__bfloat162float(wb0.x), h1-__bfloat162float(wb0.y));
        *(uint32_t*)&g_hhi[r2*256+col] = w1;
        *(uint32_t*)&g_hlo[r2*256+col] = pkbf(h2-__bfloat162float(wb1.x), h3-__bfloat162float(wb1.y));
    }
}

// ---------------- K2: fused q/k/v = h@W + b (RoPE q,k; V -> g_vt) --------
__global__ __launch_bounds__(256) void k_qkv_f(
    const float* __restrict__ bq, const float* __restrict__ bk,
    const float* __restrict__ bv)
{
    MG2_PROLOG
    {   // stage A (pre-split) via cp.async
        const int arow = tid & 63, part = tid >> 6;
        const __nv_bfloat16* shh = g_hhi + (size_t)(row0+arow)*256 + part*64;
        const __nv_bfloat16* sll = g_hlo + (size_t)(row0+arow)*256 + part*64;
        uint32_t dh = (uint32_t)__cvta_generic_to_shared(AhiP + part*4608 + arow*72);
        uint32_t dl = (uint32_t)__cvta_generic_to_shared(AloP + part*4608 + arow*72);
        #pragma unroll
        for (int t = 0; t < 8; t++) { CP16(dh + t*16, shh + t*8); CP16(dl + t*16, sll + t*8); }
    }
    MG2_STAGE_W(0, g_wthi + 65536, g_wtlo + 65536, 0)
    CPCOMMIT();

    const int gr1 = row0 + m0 + grp;
    const int b = gr1 >> 11, s1 = gr1 & 2047, s2 = s1 + 8;

    for (int c = 0; c < 12; c++) {
        CPWAIT0();
        __syncthreads();
        if (c < 11) {
            int cn = c + 1;
            MG2_STAGE_W(cn&1, g_wthi + (1 + (cn>>2))*65536, g_wtlo + (1 + (cn>>2))*65536, (cn&3)*64)
            CPCOMMIT();
        }
        MG2_COMPUTE(c&3, c&1)
        if ((c & 3) == 3) {
            const int which = c >> 2;
            if (which < 2) {
                const float* bias = (which == 0) ? bq : bk;
                float* outp = (which == 0) ? g_q : g_k;
                #pragma unroll
                for (int j = 0; j < 16; j++) {
                    int col = nb + j*8 + qd*2;
                    int hh = col >> 6, j2 = (col & 63) >> 1;
                    float2 bb = *(const float2*)&bias[col];
                    float sn1 = g_sin[s1*32 + j2], cs1 = g_cos[s1*32 + j2];
                    float sn2 = g_sin[s2*32 + j2], cs2 = g_cos[s2*32 + j2];
                    size_t base1 = ((size_t)(b*H_ + hh)*S_ + s1) * HD_;
                    size_t base2 = ((size_t)(b*H_ + hh)*S_ + s2) * HD_;
                    float t0 = acc[j][0]+bb.x, t1 = acc[j][1]+bb.y;
                    outp[base1 + j2]      = t0*cs1 - t1*sn1;
                    outp[base1 + 32 + j2] = t1*cs1 + t0*sn1;
                    float u0 = acc[j][2]+bb.x, u1 = acc[j][3]+bb.y;
                    outp[base2 + j2]      = u0*cs2 - u1*sn2;
                    outp[base2 + 32 + j2] = u1*cs2 + u0*sn2;
                }
                #pragma unroll
                for (int j = 0; j < 16; j++)
                    acc[j][0]=acc[j][1]=acc[j][2]=acc[j][3]=0.f;
            } else {
                // V epilogue: smem-staged bf16 transpose, reuse A region
                __syncthreads();
                __nv_bfloat16* Vts = (__nv_bfloat16*)smc;  // [64][264]
                #pragma unroll
                for (int j = 0; j < 16; j++) {
                    int col = nb + j*8 + qd*2;
                    float2 bb = *(const float2*)&bv[col];
                    *(uint32_t*)&Vts[(m0+grp)*264 + col]   = pkbf(acc[j][0]+bb.x, acc[j][1]+bb.y);
                    *(uint32_t*)&Vts[(m0+grp+8)*264 + col] = pkbf(acc[j][2]+bb.x, acc[j][3]+bb.y);
                }
                __syncthreads();
                const int hh = tid >> 6, dd = tid & 63;
                const int s0 = row0 & 2047, bb2 = row0 >> 11;
                __nv_bfloat16 buf[64];
                #pragma unroll 8
                for (int s = 0; s < 64; s++) buf[s] = Vts[s*264 + tid];
                __nv_bfloat16* dst = &g_vt[((size_t)(bb2*H_ + hh)*HD_ + dd)*S_ + s0];
                #pragma unroll
                for (int t = 0; t < 8; t++)
                    *(uint4*)&dst[t*8] = *(uint4*)&buf[t*8];
            }
        }
    }
}

// ---------------- K3: mma.sync bf16 flash attention, pipelined -----------
// dynamic smem: Qsm[128][72] | Ksm[2][64][72] | Vt[2][64][72] | sidx[128]
#define AT_SMEM_BYTES (18432 + 18432 + 18432 + 512)

__global__ __launch_bounds__(256) void k_attn_mma()
{
    extern __shared__ char sma[];
    __nv_bfloat16 (*Qsm)[72] = (__nv_bfloat16 (*)[72])(sma);
    __nv_bfloat16* KsmB = (__nv_bfloat16*)(sma + 18432);  // [buf][64][72]
    __nv_bfloat16* VtB  = (__nv_bfloat16*)(sma + 36864);  // [buf][64][72]
    int* sidx = (int*)(sma + 55296);

    const int tid  = threadIdx.x;
    const int w    = tid >> 5;
    const int lane = tid & 31;
    const int grp  = lane >> 2;
    const int qd   = lane & 3;
    const int b = blockIdx.z, hh = blockIdx.y;
    const int q0 = blockIdx.x * 128;
    const int cnt = g_cnt[b];
    if (q0 >= cnt) return;
    const size_t bhbase = (size_t)(b*H_ + hh) * S_ * HD_;
    const size_t vtbase = (size_t)(b*H_ + hh) * HD_ * S_;

    if (tid < 128) {
        int qi = q0 + tid;
        sidx[tid] = g_idx[b*S_ + (qi < cnt ? qi : cnt - 1)];
    }
    __syncthreads();

    const int rq = tid >> 4, d4 = tid & 15;
    {   // stage Q (gathered) bf16, 0.125 folded
        #pragma unroll
        for (int t = 0; t < 8; t++) {
            int r = rq + 16*t;
            float4 a = *(const float4*)&g_q[bhbase + (size_t)sidx[r]*HD_ + d4*4];
            *(uint2*)&Qsm[r][d4*4] = make_uint2(pkbf(a.x*0.125f, a.y*0.125f),
                                                pkbf(a.z*0.125f, a.w*0.125f));
        }
    }
    // prologue: K0 -> regs -> Ksm[0]; V0 via cp.async
    float4 kreg[4];
    #pragma unroll
    for (int t = 0; t < 4; t++)
        kreg[t] = *(const float4*)&g_k[bhbase + (size_t)(rq + 16*t)*HD_ + d4*4];
    {
        __nv_bfloat16* K0 = KsmB;
        #pragma unroll
        for (int t = 0; t < 4; t++)
            *(uint2*)&K0[(rq + 16*t)*72 + d4*4] =
                make_uint2(pkbf(kreg[t].x, kreg[t].y), pkbf(kreg[t].z, kreg[t].w));
    }
    const int kq8 = tid & 7, dd8 = tid >> 3;
    {
        #pragma unroll
        for (int t = 0; t < 2; t++) {
            int d = dd8 + 32*t;
            uint32_t dst = (uint32_t)__cvta_generic_to_shared(VtB + d*72 + kq8*8);
            CP16(dst, &g_vt[vtbase + (size_t)d*S_ + kq8*8]);
        }
        CPCOMMIT();
    }
    __syncthreads();

    uint32_t qa[4][4];
    #pragma unroll
    for (int c = 0; c < 4; c++) {
        qa[c][0] = *(const uint32_t*)&Qsm[w*16 + grp    ][c*16 + qd*2];
        qa[c][1] = *(const uint32_t*)&Qsm[w*16 + grp + 8][c*16 + qd*2];
        qa[c][2] = *(const uint32_t*)&Qsm[w*16 + grp    ][c*16 + qd*2 + 8];
        qa[c][3] = *(const uint32_t*)&Qsm[w*16 + grp + 8][c*16 + qd*2 + 8];
    }

    float ofr[8][4];
    #pragma unroll
    for (int nd = 0; nd < 8; nd++)
        #pragma unroll
        for (int i = 0; i < 4; i++) ofr[nd][i] = 0.f;
    float l_lo = 0.f, l_hi = 0.f;

    for (int kt = 0; kt < 32; kt++) {
        const int buf = kt & 1;
        CPWAIT0();
        __syncthreads();
        if (kt < 31) {
            // issue next V tile; prefetch next K tile into regs
            #pragma unroll
            for (int t = 0; t < 2; t++) {
                int d = dd8 + 32*t;
                uint32_t dst = (uint32_t)__cvta_generic_to_shared(VtB + (buf^1)*4608 + d*72 + kq8*8);
                CP16(dst, &g_vt[vtbase + (size_t)d*S_ + (kt+1)*64 + kq8*8]);
            }
            CPCOMMIT();
            const size_t kb = bhbase + (size_t)((kt+1)*64) * HD_;
            #pragma unroll
            for (int t = 0; t < 4; t++)
                kreg[t] = *(const float4*)&g_k[kb + (size_t)(rq + 16*t)*HD_ + d4*4];
        }

        const __nv_bfloat16* Ks = KsmB + buf*4608;
        const __nv_bfloat16* Vs = VtB  + buf*4608;

        float sfr[8][4];
        #pragma unroll
        for (int j = 0; j < 8; j++) {
            sfr[j][0] = sfr[j][1] = sfr[j][2] = sfr[j][3] = 0.f;
            #pragma unroll
            for (int c = 0; c < 4; c++) {
                uint32_t b0 = *(const uint32_t*)&Ks[(j*8 + grp)*72 + c*16 + qd*2];
                uint32_t b1 = *(const uint32_t*)&Ks[(j*8 + grp)*72 + c*16 + qd*2 + 8];
                mma_bf16(sfr[j], qa[c], b0, b1);
            }
        }

        uint32_t pa[4][4];
        #pragma unroll
        for (int j = 0; j < 8; j++) {
            float p0 = __expf(sfr[j][0]), p1 = __expf(sfr[j][1]);
            float p2 = __expf(sfr[j][2]), p3 = __expf(sfr[j][3]);
            l_lo += p0 + p1;
            l_hi += p2 + p3;
            int kc = j >> 1;
            if ((j & 1) == 0) { pa[kc][0] = pkbf(p0, p1); pa[kc][1] = pkbf(p2, p3); }
            else              { pa[kc][2] = pkbf(p0, p1); pa[kc][3] = pkbf(p2, p3); }
        }

        #pragma unroll
        for (int nd = 0; nd < 8; nd++) {
            #pragma unroll
            for (int kc = 0; kc < 4; kc++) {
                uint32_t b0 = *(const uint32_t*)&Vs[(nd*8 + grp)*72 + kc*16 + qd*2];
                uint32_t b1 = *(const uint32_t*)&Vs[(nd*8 + grp)*72 + kc*16 + qd*2 + 8];
                mma_bf16(ofr[nd], pa[kc], b0, b1);
            }
        }

        if (kt < 31) {   // stage prefetched K into the other buffer
            __nv_bfloat16* Kn = KsmB + (buf^1)*4608;
            #pragma unroll
            for (int t = 0; t < 4; t++)
                *(uint2*)&Kn[(rq + 16*t)*72 + d4*4] =
                    make_uint2(pkbf(kreg[t].x, kreg[t].y), pkbf(kreg[t].z, kreg[t].w));
        }
    }

    #pragma unroll
    for (int o = 1; o < 4; o <<= 1) {
        l_lo += __shfl_xor_sync(0xffffffffu, l_lo, o);
        l_hi += __shfl_xor_sync(0xffffffffu, l_hi, o);
    }
    const float inv_lo = 1.0f / l_lo, inv_hi = 1.0f / l_hi;

    const int r_lo = w*16 + grp, r_hi = r_lo + 8;
    const bool ok_lo = (q0 + r_lo < cnt), ok_hi = (q0 + r_hi < cnt);
    const size_t o_lo = bhbase + (size_t)sidx[r_lo]*HD_;
    const size_t o_hi = bhbase + (size_t)sidx[r_hi]*HD_;
    #pragma unroll
    for (int nd = 0; nd < 8; nd++) {
        if (ok_lo)
            *(float2*)&g_o[o_lo + nd*8 + qd*2] =
                make_float2(ofr[nd][0]*inv_lo, ofr[nd][1]*inv_lo);
        if (ok_hi)
            *(float2*)&g_o[o_hi + nd*8 + qd*2] =
                make_float2(ofr[nd][2]*inv_hi, ofr[nd][3]*inv_hi);
    }
}

// ---------------- K4: y = x2 + LN(x2), x2 = attn_out@wo + bo + x1 --------
__global__ __launch_bounds__(256) void k_out_ln(
    const float* __restrict__ bo,
    const float* __restrict__ g2, const float* __restrict__ be2,
    float* __restrict__ Y)
{
    MG2_PROLOG
    const int bI = row0 >> 11, sI0 = row0 & 2047;
    MG2_STAGE_A_F32(
        *(const float4*)&g_o[((size_t)(bI*H_ + (kg >> 6))*S_ + sI0 + arow)*HD_ + (kg & 63)])
    MG2_STAGE_W(0, g_wthi + 4*65536, g_wtlo + 4*65536, 0)
    CPCOMMIT();
    for (int c = 0; c < 4; c++) {
        CPWAIT0();
        __syncthreads();
        if (c < 3) { MG2_STAGE_W((c+1)&1, g_wthi + 4*65536, g_wtlo + 4*65536, (c+1)*64) CPCOMMIT(); }
        MG2_COMPUTE(c, c&1)
    }
    __syncthreads();

    float s1a=0,s2a=0,s1b=0,s2b=0;
    const size_t r1 = (size_t)row0 + m0 + grp, r2 = r1 + 8;
    #pragma unroll
    for (int j = 0; j < 16; j++) {
        int col = nb + j*8 + qd*2;
        float2 bb = *(const float2*)&bo[col];
        float2 ra = *(const float2*)&g_x1[r1*256+col];
        float2 rbv = *(const float2*)&g_x1[r2*256+col];
        acc[j][0]+=bb.x+ra.x;  acc[j][1]+=bb.y+ra.y;
        acc[j][2]+=bb.x+rbv.x; acc[j][3]+=bb.y+rbv.y;
        s1a += acc[j][0]+acc[j][1]; s2a += acc[j][0]*acc[j][0]+acc[j][1]*acc[j][1];
        s1b += acc[j][2]+acc[j][3]; s2b += acc[j][2]*acc[j][2]+acc[j][3]*acc[j][3];
    }
    #pragma unroll
    for (int o = 1; o < 4; o <<= 1) {
        s1a += __shfl_xor_sync(~0u,s1a,o); s2a += __shfl_xor_sync(~0u,s2a,o);
        s1b += __shfl_xor_sync(~0u,s1b,o); s2b += __shfl_xor_sync(~0u,s2b,o);
    }
    float2* psum = (float2*)smc;
    if (qd == 0) {
        psum[(m0+grp)*2 + (w>>2)]   = make_float2(s1a, s2a);
        psum[(m0+grp+8)*2 + (w>>2)] = make_float2(s1b, s2b);
    }
    __syncthreads();
    float2 pa0 = psum[(m0+grp)*2],   pa1 = psum[(m0+grp)*2+1];
    float2 pb0 = psum[(m0+grp+8)*2], pb1 = psum[(m0+grp+8)*2+1];
    float mean_a = (pa0.x+pa1.x)*(1.f/256.f);
    float rsa = rsqrtf((pa0.y+pa1.y)*(1.f/256.f) - mean_a*mean_a + 1e-5f);
    float mean_b = (pb0.x+pb1.x)*(1.f/256.f);
    float rsb = rsqrtf((pb0.y+pb1.y)*(1.f/256.f) - mean_b*mean_b + 1e-5f);
    #pragma unroll
    for (int j = 0; j < 16; j++) {
        int col = nb + j*8 + qd*2;
        float2 gg = *(const float2*)&g2[col], ee = *(const float2*)&be2[col];
        float y0 = acc[j][0] + (acc[j][0]-mean_a)*rsa*gg.x + ee.x;
        float y1 = acc[j][1] + (acc[j][1]-mean_a)*rsa*gg.y + ee.y;
        float y2 = acc[j][2] + (acc[j][2]-mean_b)*rsb*gg.x + ee.x;
        float y3 = acc[j][3] + (acc[j][3]-mean_b)*rsb*gg.y + ee.y;
        *(float2*)&Y[r1*256+col] = make_float2(y0, y1);
        *(float2*)&Y[r2*256+col] = make_float2(y2, y3);
    }
}

// ---------------- launch --------------------------------------------------
extern "C" void kernel_launch(void* const* d_in, const int* in_sizes, int n_in,
                              void* d_out, int out_size) {
    const float* x    = (const float*)d_in[0];
    const int*   mask = (const int*)  d_in[1];
    const float* w_in = (const float*)d_in[2];
    const float* b_in = (const float*)d_in[3];
    const float* g1   = (const float*)d_in[4];
    const float* be1  = (const float*)d_in[5];
    const float* wq   = (const float*)d_in[6];
    const float* bq   = (const float*)d_in[7];
    const float* wk   = (const float*)d_in[8];
    const float* bk   = (const float*)d_in[9];
    const float* wv   = (const float*)d_in[10];
    const float* bv   = (const float*)d_in[11];
    const float* wo   = (const float*)d_in[12];
    const float* bo   = (const float*)d_in[13];
    const float* g2   = (const float*)d_in[14];
    const float* be2  = (const float*)d_in[15];
    float* y = (float*)d_out;

    cudaFuncSetAttribute(k_in_ln,   cudaFuncAttributeMaxDynamicSharedMemorySize, MG2_SMEM_BYTES);
    cudaFuncSetAttribute(k_qkv_f,   cudaFuncAttributeMaxDynamicSharedMemorySize, MG2_SMEM_BYTES);
    cudaFuncSetAttribute(k_out_ln,  cudaFuncAttributeMaxDynamicSharedMemorySize, MG2_SMEM_BYTES);
    cudaFuncSetAttribute(k_attn_mma, cudaFuncAttributeMaxDynamicSharedMemorySize, AT_SMEM_BYTES);

    k_rope_tab <<<256, 256>>>();
    k_wsplit   <<<dim3(256, 5), 256>>>(w_in, wq, wk, wv, wo);
    k_prep     <<<B_, 256>>>(mask);
    k_in_ln    <<<NROWS/64, 256, MG2_SMEM_BYTES>>>(x, b_in, g1, be1);
    k_qkv_f    <<<NROWS/64, 256, MG2_SMEM_BYTES>>>(bq, bk, bv);
    k_fillmean <<<dim3(H_, B_), 256>>>(mask);
    k_attn_mma <<<dim3(S_/128, H_, B_), 256, AT_SMEM_BYTES>>>();
    k_out_ln   <<<NROWS/64, 256, MG2_SMEM_BYTES>>>(bo, g2, be2, y);
}